// round 7
// baseline (speedup 1.0000x reference)
#include <cuda_runtime.h>
#include <cuda_bf16.h>
#include <cstdint>

#define L     768
#define CIN   384
#define CO    32
#define NO    128
#define EPS   1e-5f

// ---------------- device scratch (no allocations allowed) ----------------
__device__ float          g_base [L * NO];               // bo[d] - (right@Wd)[i,d]
__device__ __nv_bfloat16  g_lh   [L * CO];               // left hi
__device__ __nv_bfloat16  g_ll   [L * CO];               // left lo
__device__ __nv_bfloat16  g_B2h  [(size_t)L * CO * NO];  // per-i B2 hi  [i][c][d]
__device__ __nv_bfloat16  g_B2l  [(size_t)L * CO * NO];  // per-i B2 lo

// ---------------- PTX helpers (family-common, sm_80+) ----------------
__device__ __forceinline__ uint32_t smem_u32(const void* p) {
    uint32_t a;
    asm("{ .reg .u64 t; cvta.to.shared.u64 t, %1; cvt.u32.u64 %0, t; }"
        : "=r"(a) : "l"(p));
    return a;
}
__device__ __forceinline__ void ldsm_x4(uint32_t* r, uint32_t addr) {
    asm volatile("ldmatrix.sync.aligned.m8n8.x4.shared.b16 {%0,%1,%2,%3}, [%4];"
                 : "=r"(r[0]), "=r"(r[1]), "=r"(r[2]), "=r"(r[3]) : "r"(addr));
}
__device__ __forceinline__ void ldsm_x4t(uint32_t* r, uint32_t addr) {
    asm volatile("ldmatrix.sync.aligned.m8n8.x4.trans.shared.b16 {%0,%1,%2,%3}, [%4];"
                 : "=r"(r[0]), "=r"(r[1]), "=r"(r[2]), "=r"(r[3]) : "r"(addr));
}
__device__ __forceinline__ void mma16816(float* d, const uint32_t* a, const uint32_t* b) {
    asm volatile(
        "mma.sync.aligned.m16n8k16.row.col.f32.bf16.bf16.f32 "
        "{%0,%1,%2,%3}, {%4,%5,%6,%7}, {%8,%9}, {%0,%1,%2,%3};"
        : "+f"(d[0]), "+f"(d[1]), "+f"(d[2]), "+f"(d[3])
        : "r"(a[0]), "r"(a[1]), "r"(a[2]), "r"(a[3]), "r"(b[0]), "r"(b[1]));
}
__device__ __forceinline__ void cp16(uint32_t dst, const void* src) {
    asm volatile("cp.async.ca.shared.global [%0], [%1], 16;"
                 :: "r"(dst), "l"(src) : "memory");
}
#define CP_COMMIT() asm volatile("cp.async.commit_group;" ::: "memory")
#define CP_WAIT0()  asm volatile("cp.async.wait_group 0;" ::: "memory")

// ============================================================================
// Kernel A (fused): per-row LayerNorm -> left/right projections ->
//   left bf16 hi/lo, base = bo - right@Wd, B2 = r*Wp + Wd (bf16 hi/lo).
// ============================================================================
__global__ __launch_bounds__(256)
void prep_kernel(const float* __restrict__ act,  const float* __restrict__ mask,
                 const float* __restrict__ gamma, const float* __restrict__ beta,
                 const float* __restrict__ Wl,   const float* __restrict__ bl,
                 const float* __restrict__ Wr,   const float* __restrict__ br,
                 const float* __restrict__ Wo,   const float* __restrict__ bo)
{
    __shared__ float sx[CIN];
    __shared__ float sred[512];
    __shared__ float sdot[256];
    __shared__ float slr[2 * CO];

    const int j = blockIdx.x;
    const int t = threadIdx.x;
    const float* arow = act + j * CIN;

    float s = 0.f, s2 = 0.f;
    for (int c = t; c < CIN; c += 256) {
        float v = arow[c];
        sx[c] = v;
        s += v; s2 += v * v;
    }
    sred[t] = s; sred[256 + t] = s2;
    __syncthreads();
    for (int off = 128; off > 0; off >>= 1) {
        if (t < off) {
            sred[t]       += sred[t + off];
            sred[256 + t] += sred[256 + t + off];
        }
        __syncthreads();
    }
    const float mean = sred[0] * (1.f / CIN);
    const float var  = sred[256] * (1.f / CIN) - mean * mean;
    const float rstd = rsqrtf(var + EPS);

    for (int c = t; c < CIN; c += 256)
        sx[c] = (sx[c] - mean) * rstd * gamma[c] + beta[c];
    __syncthreads();

    // Projections: lr = t>>7, q = (t>>5)&3, c = t&31 (lane-consecutive c)
    {
        const int lr = t >> 7;
        const int q  = (t >> 5) & 3;
        const int c  = t & 31;
        const float* W = lr ? Wr : Wl;
        const int ci0  = q * (CIN / 4);
        float d0 = 0.f, d1 = 0.f;
        #pragma unroll 4
        for (int ci = ci0; ci < ci0 + CIN / 4; ci += 2) {
            d0 += sx[ci]     * W[ci * CO + c];
            d1 += sx[ci + 1] * W[(ci + 1) * CO + c];
        }
        sdot[t] = d0 + d1;
    }
    __syncthreads();
    if (((t >> 5) & 3) == 0) {
        const int lr = t >> 7;
        const int c  = t & 31;
        const float bias = lr ? br[c] : bl[c];
        const float val  = mask[j] *
            (sdot[t] + sdot[t + 32] + sdot[t + 64] + sdot[t + 96] + bias);
        slr[lr * CO + c] = val;
        if (lr == 0) {
            __nv_bfloat16 h = __float2bfloat16_rn(val);
            g_lh[j * CO + c] = h;
            g_ll[j * CO + c] = __float2bfloat16_rn(val - __bfloat162float(h));
        }
    }
    __syncthreads();

    // base[j,d] = bo[d] - sum_c right[j,c]*Wd[c,d]
    if (t < 128) {
        const int d = t;
        float bm = 0.f;
        #pragma unroll
        for (int c = 0; c < CO; c++)
            bm += slr[CO + c] * Wo[(CO + c) * NO + d];
        g_base[j * NO + d] = bo[d] - bm;
    }

    // B2[j][c][d] = right[j,c]*Wp[c,d] + Wd[c,d], hi/lo split
    {
        const int d  = t & 127;
        const int c0 = (t >> 7) * 16;
        __nv_bfloat16* bh  = g_B2h + ((size_t)j * CO) * NO + d;
        __nv_bfloat16* bl2 = g_B2l + ((size_t)j * CO) * NO + d;
        #pragma unroll 4
        for (int c = c0; c < c0 + 16; c++) {
            float v = slr[CO + c] * Wo[c * NO + d] + Wo[(CO + c) * NO + d];
            __nv_bfloat16 h = __float2bfloat16_rn(v);
            bh[c * NO]  = h;
            bl2[c * NO] = __float2bfloat16_rn(v - __bfloat162float(h));
        }
    }
}

// ============================================================================
// Kernel B: block = (i, half); 3 j-tiles of 128, cp.async double-buffered sA.
// mma bf16 hi/lo (K=96 logical), B-fragment reuse (16 ldsm_B/tile),
// smem-staged epilogue -> fully coalesced STG.128.
// ============================================================================
#define SA_STRIDE 72
#define SB_STRIDE 136
#define SA_BYTES  (128 * SA_STRIDE * 2)            // 18432
#define SB_OFF    (2 * SA_BYTES)                   // 36864
#define SE_OFF    (SB_OFF + 64 * SB_STRIDE * 2)    // 54272
#define SE_STRIDE 132                              // floats (128 + 4 pad)
#define SMEM_TOTAL (SE_OFF + 64 * SE_STRIDE * 4)   // 88064

__global__ __launch_bounds__(256, 2)
void big_kernel(float* __restrict__ out)
{
    extern __shared__ char smem[];
    const uint32_t smemBase = smem_u32(smem);
    float* sE = (float*)(smem + SE_OFF);

    const int t    = threadIdx.x;
    const int i    = blockIdx.x;
    const int half = blockIdx.y;
    const int lane = t & 31;
    const int wid  = t >> 5;
    const int mStrip = wid & 3;
    const int mOff = mStrip * 32;
    const int nOff = (wid >> 2) * 64;

    // ---- prologue: prefetch tile 0 sA via cp.async ----
    {
        const int jt = half * 384;
        #pragma unroll
        for (int idx = t; idx < 1024; idx += 256) {
            const int j  = idx >> 3;
            const int s  = (idx >> 2) & 1;
            const int ch = idx & 3;
            const void* src = s ? (const void*)(g_ll + (jt + j) * CO + ch * 8)
                                : (const void*)(g_lh + (jt + j) * CO + ch * 8);
            cp16(smemBase + (j * SA_STRIDE + s * 32 + ch * 8) * 2, src);
        }
        CP_COMMIT();
    }

    // ---- stage sB (once per block) ----
    {
        const uint4* srcH = (const uint4*)(g_B2h + (size_t)i * CO * NO);
        const uint4* srcL = (const uint4*)(g_B2l + (size_t)i * CO * NO);
        #pragma unroll
        for (int idx = t; idx < 1024; idx += 256) {
            const int r  = idx >> 4;
            const int ch = idx & 15;
            const uint4 v = (r < 32) ? srcH[r * 16 + ch] : srcL[(r - 32) * 16 + ch];
            *(uint4*)(smem + SB_OFF + (r * SB_STRIDE + ch * 8) * 2) = v;
        }
    }

    // ---- base in registers (constant across tiles) ----
    float2 baseR[8];
    {
        const float* bp = g_base + i * NO + nOff + (lane & 3) * 2;
        #pragma unroll
        for (int nt = 0; nt < 8; nt++)
            baseR[nt] = *(const float2*)(bp + nt * 8);
    }

    const uint32_t bAddr0 = smemBase + SB_OFF +
        ((lane & 15) * SB_STRIDE + nOff + (lane >> 4) * 8) * 2;
    const uint32_t aLaneOff = ((mOff + (lane & 15)) * SA_STRIDE + (lane >> 4) * 8) * 2;

    #pragma unroll 1
    for (int tt = 0; tt < 3; tt++) {
        CP_WAIT0();
        __syncthreads();

        // prefetch next tile (overlaps compute)
        if (tt < 2) {
            const int jt = (half * 3 + tt + 1) * 128;
            const uint32_t dstB = smemBase + ((tt + 1) & 1) * SA_BYTES;
            #pragma unroll
            for (int idx = t; idx < 1024; idx += 256) {
                const int j  = idx >> 3;
                const int s  = (idx >> 2) & 1;
                const int ch = idx & 3;
                const void* src = s ? (const void*)(g_ll + (jt + j) * CO + ch * 8)
                                    : (const void*)(g_lh + (jt + j) * CO + ch * 8);
                cp16(dstB + (j * SA_STRIDE + s * 32 + ch * 8) * 2, src);
            }
            CP_COMMIT();
        }

        const uint32_t aAddr0 = smemBase + (tt & 1) * SA_BYTES + aLaneOff;

        float acc[2][8][4];
        #pragma unroll
        for (int nt = 0; nt < 8; nt++) {
            #pragma unroll
            for (int mt = 0; mt < 2; mt++) {
                acc[mt][nt][0] = baseR[nt].x; acc[mt][nt][1] = baseR[nt].y;
                acc[mt][nt][2] = baseR[nt].x; acc[mt][nt][3] = baseR[nt].y;
            }
        }

        uint32_t afP[2][4], afT[2][4], bf[4][4];
        #define LOAD_A(dst, kk) { \
            ldsm_x4(dst[0], aAddr0 + (uint32_t)((kk) * 2)); \
            ldsm_x4(dst[1], aAddr0 + (uint32_t)((16 * SA_STRIDE + (kk)) * 2)); }
        #define LOAD_B(kk) { \
            _Pragma("unroll") \
            for (int q = 0; q < 4; q++) \
                ldsm_x4t(bf[q], bAddr0 + (uint32_t)(((kk) * SB_STRIDE + q * 16) * 2)); }
        #define MMA_ALL(af) { \
            _Pragma("unroll") \
            for (int mt = 0; mt < 2; mt++) \
                _Pragma("unroll") \
                for (int nt = 0; nt < 8; nt++) \
                    mma16816(acc[mt][nt], af[mt], &bf[nt >> 1][(nt & 1) * 2]); }

        // B fragments reused: (lh0,ll0)*bh0, lh0*bl0, (lh1,ll1)*bh1, lh1*bl1
        LOAD_A(afP, 0);  LOAD_B(0);  MMA_ALL(afP);
        LOAD_A(afT, 32);             MMA_ALL(afT);
                         LOAD_B(32); MMA_ALL(afP);
        LOAD_A(afP, 16); LOAD_B(16); MMA_ALL(afP);
        LOAD_A(afT, 48);             MMA_ALL(afT);
                         LOAD_B(48); MMA_ALL(afP);

        #undef LOAD_A
        #undef LOAD_B
        #undef MMA_ALL

        // ---- epilogue: stage halves (64 rows) through smem, coalesced STG.128 ----
        const int jt = (half * 3 + tt) * 128;
        #pragma unroll
        for (int h = 0; h < 2; h++) {
            if ((mStrip >> 1) == h) {
                const int rbase = mOff - 64 * h + (lane >> 2);  // 0..39
                #pragma unroll
                for (int mt = 0; mt < 2; mt++) {
                    #pragma unroll
                    for (int nt = 0; nt < 8; nt++) {
                        float* p = sE + (rbase + 16 * mt) * SE_STRIDE
                                      + nOff + nt * 8 + (lane & 3) * 2;
                        *(float2*)p = make_float2(acc[mt][nt][0], acc[mt][nt][1]);
                        *(float2*)(p + 8 * SE_STRIDE) =
                            make_float2(acc[mt][nt][2], acc[mt][nt][3]);
                    }
                }
            }
            __syncthreads();
            // all warps: warp w stores rows [8w, 8w+8) of this half
            {
                const int rr = lane >> 3;          // 0..3
                const int cc = (lane & 7) * 4;     // float offset in 32-float chunk
                float* outT = out + ((size_t)i * L + jt + 64 * h) * NO;
                #pragma unroll
                for (int p2 = 0; p2 < 2; p2++) {
                    const int r = wid * 8 + 4 * p2 + rr;
                    const float* srow = sE + r * SE_STRIDE;
                    float* orow = outT + (size_t)r * NO;
                    #pragma unroll
                    for (int c4 = 0; c4 < 4; c4++)
                        *(float4*)(orow + c4 * 32 + cc) =
                            *(const float4*)(srow + c4 * 32 + cc);
                }
            }
            if (h == 0) __syncthreads();   // buffer reuse for half 1
        }
    }
}

// ============================================================================
extern "C" void kernel_launch(void* const* d_in, const int* in_sizes, int n_in,
                              void* d_out, int out_size)
{
    (void)in_sizes; (void)n_in; (void)out_size;
    const float* act   = (const float*)d_in[0];
    const float* mask  = (const float*)d_in[1];
    const float* gamma = (const float*)d_in[2];
    const float* beta  = (const float*)d_in[3];
    const float* Wl    = (const float*)d_in[4];
    const float* bl    = (const float*)d_in[5];
    const float* Wr    = (const float*)d_in[6];
    const float* br    = (const float*)d_in[7];
    const float* Wo    = (const float*)d_in[8];
    const float* bo    = (const float*)d_in[9];
    float* out = (float*)d_out;

    static bool attr_set = false;
    if (!attr_set) {
        cudaFuncSetAttribute(big_kernel,
                             cudaFuncAttributeMaxDynamicSharedMemorySize, SMEM_TOTAL);
        attr_set = true;
    }

    prep_kernel<<<L, 256>>>(act, mask, gamma, beta, Wl, bl, Wr, br, Wo, bo);

    dim3 grid(L, 2);
    big_kernel<<<grid, 256, SMEM_TOTAL>>>(out);
}

// round 8
// speedup vs baseline: 1.2932x; 1.2932x over previous
#include <cuda_runtime.h>
#include <cuda_bf16.h>
#include <cstdint>

#define L     768
#define CIN   384
#define CO    32
#define NO    128
#define EPS   1e-5f

// ---------------- device scratch (no allocations allowed) ----------------
__device__ float          g_base [L * NO];               // bo[d] - (right@Wd)[i,d]
__device__ __nv_bfloat16  g_lh   [L * CO];               // left hi
__device__ __nv_bfloat16  g_ll   [L * CO];               // left lo
__device__ __nv_bfloat16  g_B2h  [(size_t)L * CO * NO];  // per-i B2 hi  [i][c][d]
__device__ __nv_bfloat16  g_B2l  [(size_t)L * CO * NO];  // per-i B2 lo

// ---------------- PTX helpers (family-common, sm_80+) ----------------
__device__ __forceinline__ uint32_t smem_u32(const void* p) {
    uint32_t a;
    asm("{ .reg .u64 t; cvta.to.shared.u64 t, %1; cvt.u32.u64 %0, t; }"
        : "=r"(a) : "l"(p));
    return a;
}
__device__ __forceinline__ void ldsm_x4(uint32_t* r, uint32_t addr) {
    asm volatile("ldmatrix.sync.aligned.m8n8.x4.shared.b16 {%0,%1,%2,%3}, [%4];"
                 : "=r"(r[0]), "=r"(r[1]), "=r"(r[2]), "=r"(r[3]) : "r"(addr));
}
__device__ __forceinline__ void ldsm_x4t(uint32_t* r, uint32_t addr) {
    asm volatile("ldmatrix.sync.aligned.m8n8.x4.trans.shared.b16 {%0,%1,%2,%3}, [%4];"
                 : "=r"(r[0]), "=r"(r[1]), "=r"(r[2]), "=r"(r[3]) : "r"(addr));
}
__device__ __forceinline__ void mma16816(float* d, const uint32_t* a, const uint32_t* b) {
    asm volatile(
        "mma.sync.aligned.m16n8k16.row.col.f32.bf16.bf16.f32 "
        "{%0,%1,%2,%3}, {%4,%5,%6,%7}, {%8,%9}, {%0,%1,%2,%3};"
        : "+f"(d[0]), "+f"(d[1]), "+f"(d[2]), "+f"(d[3])
        : "r"(a[0]), "r"(a[1]), "r"(a[2]), "r"(a[3]), "r"(b[0]), "r"(b[1]));
}
__device__ __forceinline__ void cp16(uint32_t dst, const void* src) {
    asm volatile("cp.async.ca.shared.global [%0], [%1], 16;"
                 :: "r"(dst), "l"(src) : "memory");
}
#define CP_COMMIT() asm volatile("cp.async.commit_group;" ::: "memory")
#define CP_WAIT0()  asm volatile("cp.async.wait_group 0;" ::: "memory")

// ============================================================================
// Kernel A (fused): per-row LayerNorm -> left/right projections ->
//   left bf16 hi/lo, base = bo - right@Wd, B2 = r*Wp + Wd (bf16 hi/lo).
// One block per row j, 256 threads. (R6 form — verified 14.5us)
// ============================================================================
__global__ __launch_bounds__(256)
void prep_kernel(const float* __restrict__ act,  const float* __restrict__ mask,
                 const float* __restrict__ gamma, const float* __restrict__ beta,
                 const float* __restrict__ Wl,   const float* __restrict__ bl,
                 const float* __restrict__ Wr,   const float* __restrict__ br,
                 const float* __restrict__ Wo,   const float* __restrict__ bo)
{
    __shared__ float sx[CIN];
    __shared__ float sred[512];
    __shared__ float sdot[256];
    __shared__ float slr[2 * CO];

    const int j = blockIdx.x;
    const int t = threadIdx.x;
    const float* arow = act + j * CIN;

    float s = 0.f, s2 = 0.f;
    for (int c = t; c < CIN; c += 256) {
        float v = arow[c];
        sx[c] = v;
        s += v; s2 += v * v;
    }
    sred[t] = s; sred[256 + t] = s2;
    __syncthreads();
    for (int off = 128; off > 0; off >>= 1) {
        if (t < off) {
            sred[t]       += sred[t + off];
            sred[256 + t] += sred[256 + t + off];
        }
        __syncthreads();
    }
    const float mean = sred[0] * (1.f / CIN);
    const float var  = sred[256] * (1.f / CIN) - mean * mean;
    const float rstd = rsqrtf(var + EPS);

    for (int c = t; c < CIN; c += 256)
        sx[c] = (sx[c] - mean) * rstd * gamma[c] + beta[c];
    __syncthreads();

    // Projections: lr = t>>7, q = (t>>5)&3, c = t&31  (lane-consecutive c)
    {
        const int lr = t >> 7;
        const int q  = (t >> 5) & 3;
        const int c  = t & 31;
        const float* W = lr ? Wr : Wl;
        const int ci0  = q * (CIN / 4);
        float dot = 0.f;
        #pragma unroll 8
        for (int ci = ci0; ci < ci0 + CIN / 4; ci++)
            dot += sx[ci] * W[ci * CO + c];
        sdot[t] = dot;
    }
    __syncthreads();
    if (((t >> 5) & 3) == 0) {   // q == 0 combines the four partials
        const int lr = t >> 7;
        const int c  = t & 31;
        const float bias = lr ? br[c] : bl[c];
        const float val  = mask[j] *
            (sdot[t] + sdot[t + 32] + sdot[t + 64] + sdot[t + 96] + bias);
        slr[lr * CO + c] = val;
        if (lr == 0) {
            __nv_bfloat16 h = __float2bfloat16_rn(val);
            g_lh[j * CO + c] = h;
            g_ll[j * CO + c] = __float2bfloat16_rn(val - __bfloat162float(h));
        }
    }
    __syncthreads();

    // base[j,d] = bo[d] - sum_c right[j,c]*Wd[c,d]
    if (t < 128) {
        const int d = t;
        float bm = 0.f;
        #pragma unroll
        for (int c = 0; c < CO; c++)
            bm += slr[CO + c] * Wo[(CO + c) * NO + d];
        g_base[j * NO + d] = bo[d] - bm;
    }

    // B2[j][c][d] = right[j,c]*Wp[c,d] + Wd[c,d], hi/lo split
    {
        const int d  = t & 127;
        const int c0 = (t >> 7) * 16;
        __nv_bfloat16* bh  = g_B2h + ((size_t)j * CO) * NO + d;
        __nv_bfloat16* bl2 = g_B2l + ((size_t)j * CO) * NO + d;
        #pragma unroll 4
        for (int c = c0; c < c0 + 16; c++) {
            float v = slr[CO + c] * Wo[c * NO + d] + Wo[(CO + c) * NO + d];
            __nv_bfloat16 h = __float2bfloat16_rn(v);
            bh[c * NO]  = h;
            bl2[c * NO] = __float2bfloat16_rn(v - __bfloat162float(h));
        }
    }
}

// ============================================================================
// Kernel B: block = (i, third); 2 j-tiles of 128, cp.async double-buffered sA.
// mma bf16 hi/lo (K=96 logical), direct STG.64 epilogue (sector-optimal,
// sync-free) with streaming hint. 2304 blocks -> 7.8 waves (tail waste ~3%).
// ============================================================================
#define SA_STRIDE 72     // bf16 elems per row (conflict-free ldmatrix)
#define SB_STRIDE 136
#define SA_BYTES  (128 * SA_STRIDE * 2)    // 18432
#define SB_OFF    (2 * SA_BYTES)           // 36864
#define SMEM_TOTAL (SB_OFF + 64 * SB_STRIDE * 2)   // 54272

__global__ __launch_bounds__(256, 2)
void big_kernel(float* __restrict__ out)
{
    extern __shared__ char smem[];
    const uint32_t smemBase = smem_u32(smem);

    const int t     = threadIdx.x;
    const int i     = blockIdx.x;
    const int third = blockIdx.y;
    const int lane  = t & 31;
    const int wid   = t >> 5;
    const int mOff  = (wid & 3) * 32;
    const int nOff  = (wid >> 2) * 64;

    // ---- prologue: prefetch tile 0 sA via cp.async ----
    {
        const int jt = third * 256;
        #pragma unroll
        for (int idx = t; idx < 1024; idx += 256) {
            const int j  = idx >> 3;
            const int s  = (idx >> 2) & 1;
            const int ch = idx & 3;
            const void* src = s ? (const void*)(g_ll + (jt + j) * CO + ch * 8)
                                : (const void*)(g_lh + (jt + j) * CO + ch * 8);
            cp16(smemBase + (j * SA_STRIDE + s * 32 + ch * 8) * 2, src);
        }
        CP_COMMIT();
    }

    // ---- stage sB (once per block; B2 is L2-resident, 12.6 MB total) ----
    {
        const uint4* srcH = (const uint4*)(g_B2h + (size_t)i * CO * NO);
        const uint4* srcL = (const uint4*)(g_B2l + (size_t)i * CO * NO);
        #pragma unroll
        for (int idx = t; idx < 1024; idx += 256) {
            const int r  = idx >> 4;
            const int ch = idx & 15;
            const uint4 v = (r < 32) ? srcH[r * 16 + ch] : srcL[(r - 32) * 16 + ch];
            *(uint4*)(smem + SB_OFF + (r * SB_STRIDE + ch * 8) * 2) = v;
        }
    }

    // ---- base in registers (constant across tiles) ----
    float2 baseR[8];
    {
        const float* bp = g_base + i * NO + nOff + (lane & 3) * 2;
        #pragma unroll
        for (int nt = 0; nt < 8; nt++)
            baseR[nt] = *(const float2*)(bp + nt * 8);
    }

    const uint32_t bAddr0 = smemBase + SB_OFF +
        ((lane & 15) * SB_STRIDE + nOff + (lane >> 4) * 8) * 2;
    const uint32_t aLaneOff = ((mOff + (lane & 15)) * SA_STRIDE + (lane >> 4) * 8) * 2;

    #pragma unroll 1
    for (int tt = 0; tt < 2; tt++) {
        CP_WAIT0();
        __syncthreads();

        // prefetch next tile into the other buffer (overlaps compute)
        if (tt < 1) {
            const int jt = (third * 2 + tt + 1) * 128;
            const uint32_t dstB = smemBase + ((tt + 1) & 1) * SA_BYTES;
            #pragma unroll
            for (int idx = t; idx < 1024; idx += 256) {
                const int j  = idx >> 3;
                const int s  = (idx >> 2) & 1;
                const int ch = idx & 3;
                const void* src = s ? (const void*)(g_ll + (jt + j) * CO + ch * 8)
                                    : (const void*)(g_lh + (jt + j) * CO + ch * 8);
                cp16(dstB + (j * SA_STRIDE + s * 32 + ch * 8) * 2, src);
            }
            CP_COMMIT();
        }

        const uint32_t aAddr0 = smemBase + (tt & 1) * SA_BYTES + aLaneOff;

        float acc[2][8][4];
        #pragma unroll
        for (int nt = 0; nt < 8; nt++) {
            #pragma unroll
            for (int mt = 0; mt < 2; mt++) {
                acc[mt][nt][0] = baseR[nt].x; acc[mt][nt][1] = baseR[nt].y;
                acc[mt][nt][2] = baseR[nt].x; acc[mt][nt][3] = baseR[nt].y;
            }
        }

        uint32_t afP[2][4], afT[2][4], bf[4][4];
        #define LOAD_A(dst, kk) { \
            ldsm_x4(dst[0], aAddr0 + (uint32_t)((kk) * 2)); \
            ldsm_x4(dst[1], aAddr0 + (uint32_t)((16 * SA_STRIDE + (kk)) * 2)); }
        #define LOAD_B(kk) { \
            _Pragma("unroll") \
            for (int q = 0; q < 4; q++) \
                ldsm_x4t(bf[q], bAddr0 + (uint32_t)(((kk) * SB_STRIDE + q * 16) * 2)); }
        #define MMA_ALL(af) { \
            _Pragma("unroll") \
            for (int mt = 0; mt < 2; mt++) \
                _Pragma("unroll") \
                for (int nt = 0; nt < 8; nt++) \
                    mma16816(acc[mt][nt], af[mt], &bf[nt >> 1][(nt & 1) * 2]); }

        // B fragments reused: (lh0,ll0)*bh0, lh0*bl0, (lh1,ll1)*bh1, lh1*bl1
        LOAD_A(afP, 0);  LOAD_B(0);  MMA_ALL(afP);
        LOAD_A(afT, 32);             MMA_ALL(afT);
                         LOAD_B(32); MMA_ALL(afP);
        LOAD_A(afP, 16); LOAD_B(16); MMA_ALL(afP);
        LOAD_A(afT, 48);             MMA_ALL(afT);
                         LOAD_B(48); MMA_ALL(afP);

        #undef LOAD_A
        #undef LOAD_B
        #undef MMA_ALL

        // ---- epilogue: direct STG.64 (sector-optimal), streaming hint ----
        const int jt = (third * 2 + tt) * 128;
        const int dBase = nOff + (lane & 3) * 2;
        float* outI = out + ((size_t)i * L + jt) * NO;
        #pragma unroll
        for (int mt = 0; mt < 2; mt++) {
            const int r0 = mOff + mt * 16 + (lane >> 2);
            float* p0 = outI + (size_t)r0 * NO;
            float* p1 = p0 + 8 * NO;
            #pragma unroll
            for (int nt = 0; nt < 8; nt++) {
                const int d = dBase + nt * 8;
                __stcs((float2*)(p0 + d), make_float2(acc[mt][nt][0], acc[mt][nt][1]));
                __stcs((float2*)(p1 + d), make_float2(acc[mt][nt][2], acc[mt][nt][3]));
            }
        }
    }
}

// ============================================================================
extern "C" void kernel_launch(void* const* d_in, const int* in_sizes, int n_in,
                              void* d_out, int out_size)
{
    (void)in_sizes; (void)n_in; (void)out_size;
    const float* act   = (const float*)d_in[0];
    const float* mask  = (const float*)d_in[1];
    const float* gamma = (const float*)d_in[2];
    const float* beta  = (const float*)d_in[3];
    const float* Wl    = (const float*)d_in[4];
    const float* bl    = (const float*)d_in[5];
    const float* Wr    = (const float*)d_in[6];
    const float* br    = (const float*)d_in[7];
    const float* Wo    = (const float*)d_in[8];
    const float* bo    = (const float*)d_in[9];
    float* out = (float*)d_out;

    static bool attr_set = false;
    if (!attr_set) {
        cudaFuncSetAttribute(big_kernel,
                             cudaFuncAttributeMaxDynamicSharedMemorySize, SMEM_TOTAL);
        attr_set = true;
    }

    prep_kernel<<<L, 256>>>(act, mask, gamma, beta, Wl, bl, Wr, br, Wo, bo);

    dim3 grid(L, 3);
    big_kernel<<<grid, 256, SMEM_TOTAL>>>(out);
}